// round 3
// baseline (speedup 1.0000x reference)
#include <cuda_runtime.h>
#include <cuda_bf16.h>
#include <cstdint>

#define N_NODES 100000
#define N_EDGES 1000000
#define D 64
#define NEG_SLOPE 0.01f

// ---------------- scratch (no allocations allowed) ----------------
__device__ int   g_degOi[N_NODES];
__device__ int   g_degIi[N_NODES];
__device__ float g_oisq [N_NODES];
__device__ float g_iisq [N_NODES];
__device__ int   g_rowptr[N_NODES];       // CSR row start (atomic-allocated)
__device__ int   g_cursor[N_NODES];       // fill cursors
__device__ int   g_total;                 // global row-offset cursor
__device__ int   g_esrc[N_EDGES];         // CSR column (src) array
__device__ float g_h1[(size_t)N_NODES * D];

// ---------------- zero degree counters + cursor ----------------
__global__ void k_zero() {
    int i = blockIdx.x * blockDim.x + threadIdx.x;
    if (i < N_NODES) { g_degOi[i] = 0; g_degIi[i] = 0; }
    if (i == 0) g_total = 0;
}

// ---------------- degree histogram (4 edges/thread) ----------------
__global__ void k_deg(const int* __restrict__ src, const int* __restrict__ dst) {
    int t = blockIdx.x * blockDim.x + threadIdx.x;
    int e0 = t * 4;
    if (e0 + 4 <= N_EDGES) {
        int4 s = *(const int4*)(src + e0);
        int4 d = *(const int4*)(dst + e0);
        atomicAdd(&g_degOi[s.x], 1); atomicAdd(&g_degOi[s.y], 1);
        atomicAdd(&g_degOi[s.z], 1); atomicAdd(&g_degOi[s.w], 1);
        atomicAdd(&g_degIi[d.x], 1); atomicAdd(&g_degIi[d.y], 1);
        atomicAdd(&g_degIi[d.z], 1); atomicAdd(&g_degIi[d.w], 1);
    } else {
        for (int e = e0; e < N_EDGES; e++) {
            atomicAdd(&g_degOi[src[e]], 1);
            atomicAdd(&g_degIi[dst[e]], 1);
        }
    }
}

// ---------------- row allocation + norms (no scan needed) ----------------
__global__ void k_alloc() {
    int i = blockIdx.x * blockDim.x + threadIdx.x;
    if (i >= N_NODES) return;
    int di = g_degIi[i];
    int row = atomicAdd(&g_total, di);   // grouping only; order irrelevant
    g_rowptr[i] = row;
    g_cursor[i] = row;
    g_oisq[i] = rsqrtf((float)max(g_degOi[i], 1));
    g_iisq[i] = rsqrtf((float)max(di, 1));
}

// ---------------- CSR fill (4 edges/thread) ----------------
__global__ void k_fill(const int* __restrict__ src, const int* __restrict__ dst) {
    int t = blockIdx.x * blockDim.x + threadIdx.x;
    int e0 = t * 4;
    if (e0 + 4 <= N_EDGES) {
        int4 s = *(const int4*)(src + e0);
        int4 d = *(const int4*)(dst + e0);
        g_esrc[atomicAdd(&g_cursor[d.x], 1)] = s.x;
        g_esrc[atomicAdd(&g_cursor[d.y], 1)] = s.y;
        g_esrc[atomicAdd(&g_cursor[d.z], 1)] = s.z;
        g_esrc[atomicAdd(&g_cursor[d.w], 1)] = s.w;
    } else {
        for (int e = e0; e < N_EDGES; e++)
            g_esrc[atomicAdd(&g_cursor[dst[e]], 1)] = src[e];
    }
}

// =====================================================================
// Fused layer kernels: CSR aggregate (4 threads/node) -> smem -> GEMM
// Block: 256 threads, 64 nodes. Aggregate loop unrolled x2 (MLP=8).
// =====================================================================

// accumulate one source row (16 floats per thread) scaled by sc
#define ACC_ROW(P, SC)                                                        \
    do {                                                                      \
        float4 v0 = __ldg((P) + l + 0);                                       \
        float4 v1 = __ldg((P) + l + 4);                                       \
        float4 v2 = __ldg((P) + l + 8);                                       \
        float4 v3 = __ldg((P) + l + 12);                                      \
        a0.x += (SC)*v0.x; a0.y += (SC)*v0.y; a0.z += (SC)*v0.z; a0.w += (SC)*v0.w; \
        a1.x += (SC)*v1.x; a1.y += (SC)*v1.y; a1.z += (SC)*v1.z; a1.w += (SC)*v1.w; \
        a2.x += (SC)*v2.x; a2.y += (SC)*v2.y; a2.z += (SC)*v2.z; a2.w += (SC)*v2.w; \
        a3.x += (SC)*v3.x; a3.y += (SC)*v3.y; a3.z += (SC)*v3.z; a3.w += (SC)*v3.w; \
    } while (0)

#define ACC_ROW_NS(P)                                                         \
    do {                                                                      \
        float4 v0 = __ldg((P) + l + 0);                                       \
        float4 v1 = __ldg((P) + l + 4);                                       \
        float4 v2 = __ldg((P) + l + 8);                                       \
        float4 v3 = __ldg((P) + l + 12);                                      \
        a0.x += v0.x; a0.y += v0.y; a0.z += v0.z; a0.w += v0.w;               \
        a1.x += v1.x; a1.y += v1.y; a1.z += v1.z; a1.w += v1.w;               \
        a2.x += v2.x; a2.y += v2.y; a2.z += v2.z; a2.w += v2.w;               \
        a3.x += v3.x; a3.y += v3.y; a3.z += v3.z; a3.w += v3.w;               \
    } while (0)

// Layer 1: agg = sum_e x[src]*oisq[src]; v = agg*iisq; h1 = lrelu(v@W1+b1)*oisq
__global__ void __launch_bounds__(256) k_layer1(
    const float* __restrict__ x, const float* __restrict__ W,
    const float* __restrict__ b)
{
    __shared__ float sW[D * D];
    __shared__ float sV[64][D + 4];
    int tid = threadIdx.x;
    int base = blockIdx.x * 64;

    for (int i = tid; i < D * D; i += 256) sW[i] = W[i];

    int g = tid >> 2, l = tid & 3;
    int gn = base + g;
    float4 a0 = {0,0,0,0}, a1 = {0,0,0,0}, a2 = {0,0,0,0}, a3 = {0,0,0,0};
    if (gn < N_NODES) {
        int start = g_rowptr[gn];
        int deg   = g_degIi[gn];
        int i = 0;
        for (; i + 2 <= deg; i += 2) {
            int s0 = __ldg(&g_esrc[start + i]);
            int s1 = __ldg(&g_esrc[start + i + 1]);
            float c0 = __ldg(&g_oisq[s0]);
            float c1 = __ldg(&g_oisq[s1]);
            const float4* p0 = (const float4*)(x + (size_t)s0 * D);
            const float4* p1 = (const float4*)(x + (size_t)s1 * D);
            ACC_ROW(p0, c0);
            ACC_ROW(p1, c1);
        }
        if (i < deg) {
            int s0 = __ldg(&g_esrc[start + i]);
            float c0 = __ldg(&g_oisq[s0]);
            const float4* p0 = (const float4*)(x + (size_t)s0 * D);
            ACC_ROW(p0, c0);
        }
        float fi = g_iisq[gn];
        a0.x*=fi; a0.y*=fi; a0.z*=fi; a0.w*=fi;
        a1.x*=fi; a1.y*=fi; a1.z*=fi; a1.w*=fi;
        a2.x*=fi; a2.y*=fi; a2.z*=fi; a2.w*=fi;
        a3.x*=fi; a3.y*=fi; a3.z*=fi; a3.w*=fi;
    }
    *(float4*)&sV[g][l*4 +  0] = a0;
    *(float4*)&sV[g][l*4 + 16] = a1;
    *(float4*)&sV[g][l*4 + 32] = a2;
    *(float4*)&sV[g][l*4 + 48] = a3;
    __syncthreads();

    // GEMM 64x64 @ 64x64, 4x4 register tile
    int nq = tid >> 4, oq = tid & 15;
    float acc[4][4];
#pragma unroll
    for (int i = 0; i < 4; i++)
#pragma unroll
        for (int j = 0; j < 4; j++) acc[i][j] = 0.f;
#pragma unroll
    for (int k = 0; k < D; k++) {
        float4 w = *(const float4*)&sW[k * D + oq * 4];
#pragma unroll
        for (int i = 0; i < 4; i++) {
            float v = sV[nq * 4 + i][k];
            acc[i][0] += v * w.x; acc[i][1] += v * w.y;
            acc[i][2] += v * w.z; acc[i][3] += v * w.w;
        }
    }
    float b4[4] = {b[oq*4+0], b[oq*4+1], b[oq*4+2], b[oq*4+3]};
#pragma unroll
    for (int i = 0; i < 4; i++) {
        int on = base + nq * 4 + i;
        if (on >= N_NODES) continue;
        float sc = __ldg(&g_oisq[on]);        // pre-scale for layer-2 gather
        float4 o;
        float y0 = acc[i][0]+b4[0]; y0 = (y0>0.f)?y0:NEG_SLOPE*y0;
        float y1 = acc[i][1]+b4[1]; y1 = (y1>0.f)?y1:NEG_SLOPE*y1;
        float y2 = acc[i][2]+b4[2]; y2 = (y2>0.f)?y2:NEG_SLOPE*y2;
        float y3 = acc[i][3]+b4[3]; y3 = (y3>0.f)?y3:NEG_SLOPE*y3;
        o.x = y0*sc; o.y = y1*sc; o.z = y2*sc; o.w = y3*sc;
        *(float4*)&g_h1[(size_t)on * D + oq * 4] = o;
    }
}

// Layer 2 + classifier
__global__ void __launch_bounds__(256) k_layer2(
    const float* __restrict__ W2, const float* __restrict__ b2,
    const float* __restrict__ Wc, const float* __restrict__ bc,
    float* __restrict__ out)
{
    __shared__ float sW[D * D];
    __shared__ float sV[64][D + 4];
    __shared__ float sWc[D * 2];
    int tid = threadIdx.x;
    int base = blockIdx.x * 64;

    for (int i = tid; i < D * D; i += 256) sW[i] = W2[i];
    if (tid < D * 2) sWc[tid] = Wc[tid];

    int g = tid >> 2, l = tid & 3;
    int gn = base + g;
    float4 a0 = {0,0,0,0}, a1 = {0,0,0,0}, a2 = {0,0,0,0}, a3 = {0,0,0,0};
    if (gn < N_NODES) {
        int start = g_rowptr[gn];
        int deg   = g_degIi[gn];
        int i = 0;
        for (; i + 2 <= deg; i += 2) {
            int s0 = __ldg(&g_esrc[start + i]);
            int s1 = __ldg(&g_esrc[start + i + 1]);
            const float4* p0 = (const float4*)(g_h1 + (size_t)s0 * D);
            const float4* p1 = (const float4*)(g_h1 + (size_t)s1 * D);
            ACC_ROW_NS(p0);
            ACC_ROW_NS(p1);
        }
        if (i < deg) {
            int s0 = __ldg(&g_esrc[start + i]);
            const float4* p0 = (const float4*)(g_h1 + (size_t)s0 * D);
            ACC_ROW_NS(p0);
        }
        float fi = g_iisq[gn];
        a0.x*=fi; a0.y*=fi; a0.z*=fi; a0.w*=fi;
        a1.x*=fi; a1.y*=fi; a1.z*=fi; a1.w*=fi;
        a2.x*=fi; a2.y*=fi; a2.z*=fi; a2.w*=fi;
        a3.x*=fi; a3.y*=fi; a3.z*=fi; a3.w*=fi;
    }
    *(float4*)&sV[g][l*4 +  0] = a0;
    *(float4*)&sV[g][l*4 + 16] = a1;
    *(float4*)&sV[g][l*4 + 32] = a2;
    *(float4*)&sV[g][l*4 + 48] = a3;
    __syncthreads();

    int nq = tid >> 4, oq = tid & 15;
    float acc[4][4];
#pragma unroll
    for (int i = 0; i < 4; i++)
#pragma unroll
        for (int j = 0; j < 4; j++) acc[i][j] = 0.f;
#pragma unroll
    for (int k = 0; k < D; k++) {
        float4 w = *(const float4*)&sW[k * D + oq * 4];
#pragma unroll
        for (int i = 0; i < 4; i++) {
            float v = sV[nq * 4 + i][k];
            acc[i][0] += v * w.x; acc[i][1] += v * w.y;
            acc[i][2] += v * w.z; acc[i][3] += v * w.w;
        }
    }
    __syncthreads();   // all sV reads done before overwrite

    float b4[4] = {b2[oq*4+0], b2[oq*4+1], b2[oq*4+2], b2[oq*4+3]};
#pragma unroll
    for (int i = 0; i < 4; i++) {
#pragma unroll
        for (int j = 0; j < 4; j++) {
            float y = acc[i][j] + b4[j];
            y = (y > 0.f) ? y : NEG_SLOPE * y;
            sV[nq * 4 + i][oq * 4 + j] = y;
        }
    }
    __syncthreads();

    if (tid < 128) {
        int n = tid >> 1, c = tid & 1;
        int on = base + n;
        if (on < N_NODES) {
            float s = bc[c];
#pragma unroll
            for (int k = 0; k < D; k++) s += sV[n][k] * sWc[k * 2 + c];
            out[(size_t)on * 2 + c] = s;
        }
    }
}

// ---------------- launch ----------------
extern "C" void kernel_launch(void* const* d_in, const int* in_sizes, int n_in,
                              void* d_out, int out_size) {
    const float* x   = (const float*)d_in[0];
    const int*   src = (const int*)  d_in[1];
    const int*   dst = (const int*)  d_in[2];
    const float* W1  = (const float*)d_in[3];
    const float* b1  = (const float*)d_in[4];
    const float* W2  = (const float*)d_in[5];
    const float* b2  = (const float*)d_in[6];
    const float* Wc  = (const float*)d_in[7];
    const float* bc  = (const float*)d_in[8];
    float* out = (float*)d_out;

    const int edgeThreads = (N_EDGES + 3) / 4;
    k_zero <<<(N_NODES + 255) / 256, 256>>>();
    k_deg  <<<(edgeThreads + 255) / 256, 256>>>(src, dst);
    k_alloc<<<(N_NODES + 255) / 256, 256>>>();
    k_fill <<<(edgeThreads + 255) / 256, 256>>>(src, dst);

    k_layer1<<<(N_NODES + 63) / 64, 256>>>(x, W1, b1);
    k_layer2<<<(N_NODES + 63) / 64, 256>>>(W2, b2, Wc, bc, out);
}